// round 4
// baseline (speedup 1.0000x reference)
#include <cuda_runtime.h>
#include <stdint.h>
#include <math.h>

#define BATCH 64
#define SEQ   256
#define DIM   1024
#define BETA_C 0.75f
#define TEMP_C 0.1f

// ---- hybrid GEMM tiling ----
#define BM 256                      // rows/CTA: 128 HMMA + 128 FFMA2
#define BN 128
#define BK 16
#define NKT (DIM / BK)              // 64 k-chunks
// stage layout (floats): A-frag 2048 | B-frag 2048 | A_t 16x132 | B_row 16x132
#define OFF_FA 0
#define OFF_FB 2048
#define OFF_AT 4096
#define OFF_BR (4096 + 16 * 132)
#define STAGE_FLOATS (4096 + 2 * 16 * 132)     // 8320
#define SMEM_TOTAL (2 * STAGE_FLOATS * 4)      // 66560 B

// ---------------- device scratch ----------------
__device__ float g_i[BATCH * DIM];
__device__ float g_iCi[BATCH * DIM];
__device__ float g_co[BATCH * DIM];
__device__ float g_E[BATCH];
__device__ float g_simn[BATCH * SEQ];
__device__ float g_sig[BATCH * SEQ];
__device__ float g_Wt[DIM * DIM];

// ---------------- K0: transpose weight ----------------
__global__ void k_transpose(const float* __restrict__ W) {
    __shared__ float t[32][33];
    int x = blockIdx.x * 32 + threadIdx.x;
    int y0 = blockIdx.y * 32;
#pragma unroll
    for (int j = 0; j < 32; j += 8)
        t[threadIdx.y + j][threadIdx.x] = W[(size_t)(y0 + threadIdx.y + j) * DIM + x];
    __syncthreads();
    int x2 = blockIdx.y * 32 + threadIdx.x;
    int y2 = blockIdx.x * 32;
#pragma unroll
    for (int j = 0; j < 32; j += 8)
        g_Wt[(size_t)(y2 + threadIdx.y + j) * DIM + x2] = t[threadIdx.x][threadIdx.y + j];
}

// ---------------- K1: gather i ----------------
__global__ void k_gather(const int* __restrict__ prompt_ids,
                         const int* __restrict__ concept_indices,
                         const uint8_t* __restrict__ initted,
                         const float* __restrict__ ema_table,
                         const float* __restrict__ text_enc) {
    int b = blockIdx.x;
    int pid = prompt_ids[b];
    int ci = concept_indices[b];
    bool init = initted[pid] != 0;
    const float* src = init ? (ema_table + (size_t)pid * DIM)
                            : (text_enc + ((size_t)b * SEQ + ci) * DIM);
    for (int d = threadIdx.x; d < DIM; d += blockDim.x)
        g_i[b * DIM + d] = src[d];
}

// ---------------- K2: small GEMMs ----------------
__global__ void k_smallgemm(const float* __restrict__ Cinv) {
    const float* __restrict__ M = (blockIdx.z == 0) ? Cinv : g_Wt;
    float* __restrict__ out = (blockIdx.z == 0) ? g_iCi : g_co;
    int d = blockIdx.x * 128 + threadIdx.x;
    int b0 = blockIdx.y * 8;
    __shared__ float ish[8][128];
    float acc[8];
#pragma unroll
    for (int r = 0; r < 8; r++) acc[r] = 0.0f;
    for (int k0 = 0; k0 < DIM; k0 += 128) {
#pragma unroll
        for (int r = 0; r < 8; r++)
            ish[r][threadIdx.x] = g_i[(b0 + r) * DIM + k0 + threadIdx.x];
        __syncthreads();
#pragma unroll 4
        for (int kk = 0; kk < 128; kk++) {
            float m = M[(size_t)(k0 + kk) * DIM + d];
#pragma unroll
            for (int r = 0; r < 8; r++) acc[r] += ish[r][kk] * m;
        }
        __syncthreads();
    }
#pragma unroll
    for (int r = 0; r < 8; r++) out[(b0 + r) * DIM + d] = acc[r];
}

// ---------------- K3: i_energy ----------------
__global__ void k_energy() {
    int b = blockIdx.x, tid = threadIdx.x;
    float s = 0.0f;
    for (int d = tid; d < DIM; d += 256)
        s += g_iCi[b * DIM + d] * g_i[b * DIM + d];
#pragma unroll
    for (int o = 16; o; o >>= 1) s += __shfl_xor_sync(0xffffffffu, s, o);
    __shared__ float red[8];
    if ((tid & 31) == 0) red[tid >> 5] = s;
    __syncthreads();
    if (tid < 8) {
        float t = red[tid];
#pragma unroll
        for (int o = 4; o; o >>= 1) t += __shfl_xor_sync(0xffu, t, o);
        if (tid == 0) g_E[b] = t;
    }
}

// ---------------- K4: sim + sigmoid ----------------
__global__ void k_sim(const float* __restrict__ text_enc) {
    int warp = threadIdx.x >> 5, lane = threadIdx.x & 31;
    int m = blockIdx.x * 8 + warp;
    int b = m >> 8;
    const float4* x = (const float4*)(text_enc + (size_t)m * DIM);
    const float4* c = (const float4*)(g_iCi + (size_t)b * DIM);
    float s = 0.0f;
#pragma unroll
    for (int it = 0; it < 8; it++) {
        int idx = it * 32 + lane;
        float4 xv = x[idx], cv = c[idx];
        s += xv.x * cv.x + xv.y * cv.y + xv.z * cv.z + xv.w * cv.w;
    }
#pragma unroll
    for (int o = 16; o; o >>= 1) s += __shfl_xor_sync(0xffffffffu, s, o);
    if (lane == 0) {
        float simn = s / g_E[b];
        g_simn[m] = simn;
        g_sig[m] = 1.0f / (1.0f + expf(-(simn - BETA_C) / TEMP_C));
    }
}

// ---------------- helpers ----------------
__device__ __forceinline__ uint32_t f2tf32(float x) {
    uint32_t r;
    asm("cvt.rna.tf32.f32 %0, %1;" : "=r"(r) : "f"(x));
    return r;
}
__device__ __forceinline__ void mma_tf32(float* c, const uint4& a, const uint2& b) {
    asm volatile(
        "mma.sync.aligned.m16n8k8.row.col.f32.tf32.tf32.f32 "
        "{%0,%1,%2,%3}, {%4,%5,%6,%7}, {%8,%9}, {%0,%1,%2,%3};"
        : "+f"(c[0]), "+f"(c[1]), "+f"(c[2]), "+f"(c[3])
        : "r"(a.x), "r"(a.y), "r"(a.z), "r"(a.w), "r"(b.x), "r"(b.y));
}
__device__ __forceinline__ unsigned long long pack2(float a) {
    unsigned long long p;
    asm("mov.b64 %0, {%1, %1};" : "=l"(p) : "f"(a));
    return p;
}
__device__ __forceinline__ void fma2(unsigned long long& c, unsigned long long a,
                                     unsigned long long b) {
    asm("fma.rn.f32x2 %0, %1, %2, %0;" : "+l"(c) : "l"(a), "l"(b));
}
__device__ __forceinline__ float2 unpack2(unsigned long long p) {
    float lo, hi;
    asm("mov.b64 {%0, %1}, %2;" : "=f"(lo), "=f"(hi) : "l"(p));
    return make_float2(lo, hi);
}

// HMMA fragment stores (validated in R3)
__device__ __forceinline__ void sts_fragA(float* base, int mrow, int k0, const float4 v) {
    int ks = k0 >> 3, krh = (k0 >> 2) & 1;
    int mt = mrow >> 4, mr = mrow & 15;
    float* p = base + OFF_FA + (((ks * 8 + mt) * 32 + ((mr & 7) << 2)) << 2) + ((mr >> 3) | (krh << 1));
    p[0] = v.x; p[4] = v.y; p[8] = v.z; p[12] = v.w;
}
__device__ __forceinline__ void sts_fragB(float* base, int nrow, int k0, const float4 v) {
    int ks = k0 >> 3, krh = (k0 >> 2) & 1;
    int nt = nrow >> 3, nr = nrow & 7;
    float* p = base + OFF_FB + (((ks * 16 + nt) * 32 + (nr << 2)) << 1) + krh;
    p[0] = v.x; p[2] = v.y; p[4] = v.z; p[6] = v.w;
}

// ---------------- K5: hybrid tensor+fma2 GEMM + fused epilogue ----------------
__global__ __launch_bounds__(256, 1) void k_main(
    const float* __restrict__ A,              // text_enc [16384][1024]
    const float* __restrict__ W,              // weight   [1024][1024]
    const int* __restrict__ prompt_ids,
    const uint8_t* __restrict__ initted,
    const float* __restrict__ outputs_table,  // [512][256][1024]
    float* __restrict__ out) {
    extern __shared__ float sf[];

    const int tid = threadIdx.x;
    const int wid = tid >> 5, lane = tid & 31;
    const int wm = wid & 1, wn = wid >> 1;
    const int m0 = blockIdx.y * BM;
    const int n0 = blockIdx.x * BN;

    // producer mapping
    const int prow = tid >> 1;           // 0..127
    const int pk = (tid & 1) * 8;        // 0 or 8
    const float* Atop = A + (size_t)(m0 + prow) * DIM + pk;
    const float* Abot = A + (size_t)(m0 + 128 + prow) * DIM + pk;
    const float* Bptr = W + (size_t)(n0 + prow) * DIM + pk;

    // HMMA accumulators (top half)
    float hacc[4][4][4];
#pragma unroll
    for (int i = 0; i < 4; i++)
#pragma unroll
        for (int j = 0; j < 4; j++)
#pragma unroll
            for (int r = 0; r < 4; r++) hacc[i][j][r] = 0.0f;
    // FFMA2 accumulators (bottom half): 8 rows x 4 n-pairs
    unsigned long long facc[8][4];
#pragma unroll
    for (int i = 0; i < 8; i++)
#pragma unroll
        for (int p = 0; p < 4; p++) facc[i][p] = 0ULL;

    float4 pat[2], pab[2], pbb[2];

    // helper lambda-ish store of one loaded set into a stage
#define STORE_STAGE(stg)                                                          \
    do {                                                                          \
        float* st = sf + (stg) * STAGE_FLOATS;                                    \
        _Pragma("unroll")                                                         \
        for (int u = 0; u < 2; u++) {                                             \
            float4 ta = make_float4(                                              \
                __uint_as_float(f2tf32(pat[u].x)), __uint_as_float(f2tf32(pat[u].y)), \
                __uint_as_float(f2tf32(pat[u].z)), __uint_as_float(f2tf32(pat[u].w))); \
            sts_fragA(st, prow, pk + u * 4, ta);                                  \
            float4 tb = make_float4(                                              \
                __uint_as_float(f2tf32(pbb[u].x)), __uint_as_float(f2tf32(pbb[u].y)), \
                __uint_as_float(f2tf32(pbb[u].z)), __uint_as_float(f2tf32(pbb[u].w))); \
            sts_fragB(st, prow, pk + u * 4, tb);                                  \
            int kb = pk + u * 4;                                                  \
            st[OFF_AT + (kb + 0) * 132 + prow] = pab[u].x;                        \
            st[OFF_AT + (kb + 1) * 132 + prow] = pab[u].y;                        \
            st[OFF_AT + (kb + 2) * 132 + prow] = pab[u].z;                        \
            st[OFF_AT + (kb + 3) * 132 + prow] = pab[u].w;                        \
            st[OFF_BR + (kb + 0) * 132 + prow] = pbb[u].x;                        \
            st[OFF_BR + (kb + 1) * 132 + prow] = pbb[u].y;                        \
            st[OFF_BR + (kb + 2) * 132 + prow] = pbb[u].z;                        \
            st[OFF_BR + (kb + 3) * 132 + prow] = pbb[u].w;                        \
        }                                                                         \
    } while (0)

    // prologue
#pragma unroll
    for (int u = 0; u < 2; u++) {
        pat[u] = *(const float4*)(Atop + u * 4);
        pab[u] = *(const float4*)(Abot + u * 4);
        pbb[u] = *(const float4*)(Bptr + u * 4);
    }
    STORE_STAGE(0);
    __syncthreads();

    const int fm = (lane >> 2) * 8;      // FFMA2 local row base within warp half
    const int fc = (lane & 3) * 8;       // FFMA2 local col base within warp cols

    for (int kt = 0; kt < NKT; kt++) {
        float* cur = sf + (kt & 1) * STAGE_FLOATS;
        if (kt + 1 < NKT) {
            int ko = (kt + 1) * BK;
#pragma unroll
            for (int u = 0; u < 2; u++) {
                pat[u] = *(const float4*)(Atop + ko + u * 4);
                pab[u] = *(const float4*)(Abot + ko + u * 4);
                pbb[u] = *(const float4*)(Bptr + ko + u * 4);
            }
        }
        // ---- HMMA (tensor pipe), 2 k8-steps ----
#pragma unroll
        for (int ks = 0; ks < 2; ks++) {
            uint4 afr[4];
            uint2 bfr[4];
#pragma unroll
            for (int i = 0; i < 4; i++)
                afr[i] = *(const uint4*)(cur + OFF_FA + (((ks * 8 + wm * 4 + i) * 32 + lane) << 2));
#pragma unroll
            for (int j = 0; j < 4; j++)
                bfr[j] = *(const uint2*)(cur + OFF_FB + (((ks * 16 + wn * 4 + j) * 32 + lane) << 1));
#pragma unroll
            for (int i = 0; i < 4; i++)
#pragma unroll
                for (int j = 0; j < 4; j++)
                    mma_tf32(hacc[i][j], afr[i], bfr[j]);
        }
        // ---- FFMA2 (fma pipe), 16 k-steps ----
#pragma unroll
        for (int k = 0; k < BK; k++) {
            const float* arow = cur + OFF_AT + k * 132 + wm * 64 + fm;
            const float* brow = cur + OFF_BR + k * 132 + wn * 32 + fc;
            float4 a0 = *(const float4*)(arow);
            float4 a1 = *(const float4*)(arow + 4);
            unsigned long long b2[4];
            b2[0] = *(const unsigned long long*)(brow);
            b2[1] = *(const unsigned long long*)(brow + 2);
            b2[2] = *(const unsigned long long*)(brow + 4);
            b2[3] = *(const unsigned long long*)(brow + 6);
            unsigned long long a2[8];
            a2[0] = pack2(a0.x); a2[1] = pack2(a0.y); a2[2] = pack2(a0.z); a2[3] = pack2(a0.w);
            a2[4] = pack2(a1.x); a2[5] = pack2(a1.y); a2[6] = pack2(a1.z); a2[7] = pack2(a1.w);
#pragma unroll
            for (int i = 0; i < 8; i++)
#pragma unroll
                for (int p = 0; p < 4; p++)
                    fma2(facc[i][p], a2[i], b2[p]);
        }
        if (kt + 1 < NKT) {
            __syncthreads();
            STORE_STAGE((kt + 1) & 1);
            __syncthreads();
        }
    }

    // ---------------- fused epilogue ----------------
    const int b = blockIdx.y;            // BM==SEQ: one batch per CTA
    const int pid = prompt_ids[b];
    const bool init = initted[pid] != 0;

    // HMMA half
    {
        float2 co2[4];
#pragma unroll
        for (int j = 0; j < 4; j++)
            co2[j] = *(const float2*)&g_co[b * DIM + n0 + wn * 32 + j * 8 + (lane & 3) * 2];
#pragma unroll
        for (int i = 0; i < 4; i++) {
            int gr0 = m0 + wm * 64 + i * 16 + (lane >> 2);
            int gr1 = gr0 + 8;
            float simn0 = g_simn[gr0], sig0 = g_sig[gr0];
            float simn1 = g_simn[gr1], sig1 = g_sig[gr1];
            const float* ot0 = outputs_table + ((size_t)pid * SEQ + (gr0 & (SEQ - 1))) * DIM;
            const float* ot1 = outputs_table + ((size_t)pid * SEQ + (gr1 & (SEQ - 1))) * DIM;
#pragma unroll
            for (int j = 0; j < 4; j++) {
                int col = n0 + wn * 32 + j * 8 + (lane & 3) * 2;
                float c0 = hacc[i][j][0], c1 = hacc[i][j][1];
                float c2 = hacc[i][j][2], c3 = hacc[i][j][3];
                float o0 = init ? ot0[col] : c0;
                float o1 = init ? ot0[col + 1] : c1;
                float o2 = init ? ot1[col] : c2;
                float o3 = init ? ot1[col + 1] : c3;
                float2 v0 = make_float2(c0 - simn0 * co2[j].x + sig0 * o0,
                                        c1 - simn0 * co2[j].y + sig0 * o1);
                float2 v1 = make_float2(c2 - simn1 * co2[j].x + sig1 * o2,
                                        c3 - simn1 * co2[j].y + sig1 * o3);
                *(float2*)&out[(size_t)gr0 * DIM + col] = v0;
                *(float2*)&out[(size_t)gr1 * DIM + col] = v1;
            }
        }
    }
    // FFMA2 half
    {
        int c0 = n0 + wn * 32 + fc;
        float4 cof0 = *(const float4*)&g_co[b * DIM + c0];
        float4 cof1 = *(const float4*)&g_co[b * DIM + c0 + 4];
#pragma unroll
        for (int i = 0; i < 8; i++) {
            int gm = m0 + 128 + wm * 64 + fm + i;
            float simn = g_simn[gm], sig = g_sig[gm];
            const float* ot = outputs_table + ((size_t)pid * SEQ + (gm & (SEQ - 1))) * DIM;
            float f[8];
            float2 t;
            t = unpack2(facc[i][0]); f[0] = t.x; f[1] = t.y;
            t = unpack2(facc[i][1]); f[2] = t.x; f[3] = t.y;
            t = unpack2(facc[i][2]); f[4] = t.x; f[5] = t.y;
            t = unpack2(facc[i][3]); f[6] = t.x; f[7] = t.y;
            const float* cop = (const float*)&cof0;
            float4 v0, v1;
            float* vp0 = (float*)&v0;
            float* vp1 = (float*)&v1;
#pragma unroll
            for (int j = 0; j < 4; j++) {
                float osel = init ? ot[c0 + j] : f[j];
                vp0[j] = f[j] - simn * cop[j] + sig * osel;
            }
            const float* cop1 = (const float*)&cof1;
#pragma unroll
            for (int j = 0; j < 4; j++) {
                float osel = init ? ot[c0 + 4 + j] : f[4 + j];
                vp1[j] = f[4 + j] - simn * cop1[j] + sig * osel;
            }
            *(float4*)&out[(size_t)gm * DIM + c0] = v0;
            *(float4*)&out[(size_t)gm * DIM + c0 + 4] = v1;
        }
    }
}

// --------------------------------- launch ---------------------------------------
extern "C" void kernel_launch(void* const* d_in, const int* in_sizes, int n_in,
                              void* d_out, int out_size) {
    const int*     prompt_ids      = (const int*)d_in[0];
    const float*   text_enc        = (const float*)d_in[1];
    const int*     concept_indices = (const int*)d_in[2];
    const float*   weight          = (const float*)d_in[3];
    const float*   C_inv           = (const float*)d_in[4];
    const uint8_t* initted         = (const uint8_t*)d_in[5];
    const float*   ema_table       = (const float*)d_in[6];
    const float*   outputs_table   = (const float*)d_in[7];
    float*         out             = (float*)d_out;

    (void)in_sizes; (void)n_in; (void)out_size;

    cudaFuncSetAttribute(k_main, cudaFuncAttributeMaxDynamicSharedMemorySize, SMEM_TOTAL);

    k_transpose<<<dim3(DIM / 32, DIM / 32), dim3(32, 8)>>>(weight);
    k_gather<<<BATCH, 256>>>(prompt_ids, concept_indices, initted, ema_table, text_enc);
    k_smallgemm<<<dim3(DIM / 128, BATCH / 8, 2), 128>>>(C_inv);
    k_energy<<<BATCH, 256>>>();
    k_sim<<<(BATCH * SEQ) / 8, 256>>>(text_enc);
    k_main<<<dim3(DIM / BN, (BATCH * SEQ) / BM), 256, SMEM_TOTAL>>>(
        text_enc, weight, prompt_ids, initted, outputs_table, out);
}